// round 3
// baseline (speedup 1.0000x reference)
#include <cuda_runtime.h>
#include <cuda_bf16.h>
#include <math.h>

#define N_NODES 50000
#define N_EDGES 600000
#define E_TOTAL (N_EDGES + N_NODES)
#define HID 128
#define N_GRAPHS 64

// ---------------- scratch (static device globals; no allocation) ----------------
__device__ float g_h[N_NODES * HID];    // GEMM output (pre-aggregation), per layer
__device__ float g_act[N_NODES * HID];  // layer activation (post aggregation + ELU)
__device__ float g_as[N_NODES];         // alpha_src per node
__device__ float g_ad[N_NODES];         // alpha_dst per node
__device__ int   g_deg[N_NODES];
__device__ int   g_rowptr[N_NODES + 1];
__device__ int   g_cursor[N_NODES];
__device__ int   g_col[E_TOTAL];        // src node per (dst-grouped) edge

// ---------------- CSR build ----------------
__global__ void k_init_deg() {
    int i = blockIdx.x * blockDim.x + threadIdx.x;
    if (i < N_NODES) g_deg[i] = 1;  // self-loop
}

__global__ void k_count(const int* __restrict__ ei) {
    int e = blockIdx.x * blockDim.x + threadIdx.x;
    if (e < N_EDGES) atomicAdd(&g_deg[ei[N_EDGES + e]], 1);
}

// single-block exclusive scan over g_deg -> g_rowptr
__global__ void k_scan() {
    __shared__ int sh[1024];
    __shared__ int carry;
    int tid = threadIdx.x;
    if (tid == 0) { carry = 0; g_rowptr[0] = 0; }
    __syncthreads();
    for (int base = 0; base < N_NODES; base += 1024) {
        int i = base + tid;
        int v = (i < N_NODES) ? g_deg[i] : 0;
        sh[tid] = v;
        __syncthreads();
        #pragma unroll
        for (int off = 1; off < 1024; off <<= 1) {
            int t = (tid >= off) ? sh[tid - off] : 0;
            __syncthreads();
            sh[tid] += t;
            __syncthreads();
        }
        int incl = sh[tid] + carry;
        if (i < N_NODES) g_rowptr[i + 1] = incl;
        __syncthreads();
        if (tid == 0) carry += sh[1023];
        __syncthreads();
    }
}

__global__ void k_cursor() {
    int i = blockIdx.x * blockDim.x + threadIdx.x;
    if (i < N_NODES) g_cursor[i] = g_rowptr[i];
}

__global__ void k_fill(const int* __restrict__ ei) {
    int idx = blockIdx.x * blockDim.x + threadIdx.x;
    if (idx < N_EDGES) {
        int src = ei[idx];
        int dst = ei[N_EDGES + idx];
        int pos = atomicAdd(&g_cursor[dst], 1);
        g_col[pos] = src;
    } else if (idx < E_TOTAL) {
        int node = idx - N_EDGES;
        int pos = atomicAdd(&g_cursor[node], 1);
        g_col[pos] = node;
    }
}

// ---------------- GEMM: C[N,128] = A[N,128] @ W[128,128] ----------------
// Tile: 64 rows x 128 cols per block, 256 threads, K-chunks of 16.
__global__ __launch_bounds__(256) void k_gemm(const float* __restrict__ X,
                                              const float* __restrict__ W,
                                              int use_x) {
    __shared__ float sA[16][65];   // [k][row], padded
    __shared__ float sB[16][128];  // [k][col]

    const float* A = use_x ? X : g_act;
    int tid = threadIdx.x;
    int tx = tid & 31;       // col group: cols tx*4 .. tx*4+3
    int ty = tid >> 5;       // row group: rows ty*8 .. ty*8+7
    int row0 = blockIdx.x * 64;

    float4 acc[8];
    #pragma unroll
    for (int i = 0; i < 8; i++) acc[i] = make_float4(0.f, 0.f, 0.f, 0.f);

    for (int kc = 0; kc < 128; kc += 16) {
        // load A tile: 64 rows x 16 k, one float4 per thread
        {
            int r = tid >> 2;        // 0..63
            int kq = tid & 3;        // 0..3  (k = kq*4..kq*4+3)
            int grow = row0 + r;
            float4 v = make_float4(0.f, 0.f, 0.f, 0.f);
            if (grow < N_NODES)
                v = *reinterpret_cast<const float4*>(&A[grow * 128 + kc + kq * 4]);
            sA[kq * 4 + 0][r] = v.x;
            sA[kq * 4 + 1][r] = v.y;
            sA[kq * 4 + 2][r] = v.z;
            sA[kq * 4 + 3][r] = v.w;
        }
        // load B tile: 16 rows x 128 cols, two float4 per thread
        {
            int r = tid >> 5;        // 0..7
            int c = (tid & 31) * 4;
            *reinterpret_cast<float4*>(&sB[r][c]) =
                *reinterpret_cast<const float4*>(&W[(kc + r) * 128 + c]);
            *reinterpret_cast<float4*>(&sB[r + 8][c]) =
                *reinterpret_cast<const float4*>(&W[(kc + r + 8) * 128 + c]);
        }
        __syncthreads();

        #pragma unroll
        for (int k = 0; k < 16; k++) {
            float4 bv = *reinterpret_cast<const float4*>(&sB[k][tx * 4]);
            #pragma unroll
            for (int i = 0; i < 8; i++) {
                float a = sA[k][ty * 8 + i];
                acc[i].x += a * bv.x;
                acc[i].y += a * bv.y;
                acc[i].z += a * bv.z;
                acc[i].w += a * bv.w;
            }
        }
        __syncthreads();
    }

    #pragma unroll
    for (int i = 0; i < 8; i++) {
        int grow = row0 + ty * 8 + i;
        if (grow < N_NODES)
            *reinterpret_cast<float4*>(&g_h[grow * 128 + tx * 4]) = acc[i];
    }
}

// ---------------- alpha: per-node dot(h, a_src), dot(h, a_dst) ----------------
__global__ __launch_bounds__(256) void k_alpha(const float* __restrict__ a_src,
                                               const float* __restrict__ a_dst) {
    int w = (blockIdx.x * blockDim.x + threadIdx.x) >> 5;
    int lane = threadIdx.x & 31;
    if (w >= N_NODES) return;
    const float4* h4 = reinterpret_cast<const float4*>(g_h);
    float4 hv = h4[w * 32 + lane];
    float4 s4 = reinterpret_cast<const float4*>(a_src)[lane];
    float4 d4 = reinterpret_cast<const float4*>(a_dst)[lane];
    float ps = hv.x * s4.x + hv.y * s4.y + hv.z * s4.z + hv.w * s4.w;
    float pd = hv.x * d4.x + hv.y * d4.y + hv.z * d4.z + hv.w * d4.w;
    #pragma unroll
    for (int off = 16; off > 0; off >>= 1) {
        ps += __shfl_xor_sync(0xffffffffu, ps, off);
        pd += __shfl_xor_sync(0xffffffffu, pd, off);
    }
    if (lane == 0) { g_as[w] = ps; g_ad[w] = pd; }
}

// ---------------- aggregation: per-dst softmax-weighted sum, +bias, ELU ----------------
__global__ __launch_bounds__(256) void k_agg(const float* __restrict__ bias) {
    int w = (blockIdx.x * blockDim.x + threadIdx.x) >> 5;
    int lane = threadIdx.x & 31;
    if (w >= N_NODES) return;

    int beg = g_rowptr[w];
    int end = g_rowptr[w + 1];
    float ad = g_ad[w];

    // pass 1: max of leaky_relu(e)
    float m = -1e30f;
    for (int e = beg + lane; e < end; e += 32) {
        int s = g_col[e];
        float v = g_as[s] + ad;
        v = v > 0.f ? v : 0.2f * v;
        m = fmaxf(m, v);
    }
    #pragma unroll
    for (int off = 16; off > 0; off >>= 1)
        m = fmaxf(m, __shfl_xor_sync(0xffffffffu, m, off));

    // pass 2: sum of exp(v - m)
    float ss = 0.f;
    for (int e = beg + lane; e < end; e += 32) {
        int s = g_col[e];
        float v = g_as[s] + ad;
        v = v > 0.f ? v : 0.2f * v;
        ss += __expf(v - m);
    }
    #pragma unroll
    for (int off = 16; off > 0; off >>= 1)
        ss += __shfl_xor_sync(0xffffffffu, ss, off);
    float inv = 1.f / (ss + 1e-16f);

    // pass 3: weighted accumulation of h[src] rows (all 32 lanes = 128 dims)
    float4 acc = make_float4(0.f, 0.f, 0.f, 0.f);
    const float4* h4 = reinterpret_cast<const float4*>(g_h);
    for (int e = beg; e < end; ++e) {
        int s = g_col[e];                 // broadcast load across warp
        float v = g_as[s] + ad;
        v = v > 0.f ? v : 0.2f * v;
        float wgt = __expf(v - m) * inv;
        float4 hv = h4[s * 32 + lane];
        acc.x += wgt * hv.x;
        acc.y += wgt * hv.y;
        acc.z += wgt * hv.z;
        acc.w += wgt * hv.w;
    }

    float4 bb = reinterpret_cast<const float4*>(bias)[lane];
    acc.x += bb.x; acc.y += bb.y; acc.z += bb.z; acc.w += bb.w;
    // ELU
    acc.x = acc.x > 0.f ? acc.x : (__expf(acc.x) - 1.f);
    acc.y = acc.y > 0.f ? acc.y : (__expf(acc.y) - 1.f);
    acc.z = acc.z > 0.f ? acc.z : (__expf(acc.z) - 1.f);
    acc.w = acc.w > 0.f ? acc.w : (__expf(acc.w) - 1.f);

    reinterpret_cast<float4*>(g_act)[w * 32 + lane] = acc;
}

// ---------------- global mean pool over sorted batch ----------------
__global__ __launch_bounds__(512) void k_pool(const int* __restrict__ batch,
                                              float* __restrict__ out) {
    int g = blockIdx.x;
    int tid = threadIdx.x;
    int sub = tid >> 7;     // 0..3
    int d = tid & 127;

    // lower_bound(batch, g) and lower_bound(batch, g+1)
    int lo = 0, hi = N_NODES;
    while (lo < hi) { int mid = (lo + hi) >> 1; if (batch[mid] < g) lo = mid + 1; else hi = mid; }
    int start = lo;
    lo = 0; hi = N_NODES;
    while (lo < hi) { int mid = (lo + hi) >> 1; if (batch[mid] < g + 1) lo = mid + 1; else hi = mid; }
    int stop = lo;

    float s = 0.f;
    for (int i = start + sub; i < stop; i += 4)
        s += g_act[i * 128 + d];

    __shared__ float sm[4][128];
    sm[sub][d] = s;
    __syncthreads();
    if (sub == 0) {
        float tot = sm[0][d] + sm[1][d] + sm[2][d] + sm[3][d];
        int cnt = stop - start;
        out[g * 128 + d] = tot / (float)(cnt > 0 ? cnt : 1);
    }
}

// ---------------- launch ----------------
extern "C" void kernel_launch(void* const* d_in, const int* in_sizes, int n_in,
                              void* d_out, int out_size) {
    const float* x     = (const float*)d_in[0];
    const int*   ei    = (const int*)d_in[1];
    const int*   batch = (const int*)d_in[2];
    const float* W[3]   = { (const float*)d_in[3], (const float*)d_in[7],  (const float*)d_in[11] };
    const float* asr[3] = { (const float*)d_in[4], (const float*)d_in[8],  (const float*)d_in[12] };
    const float* ads[3] = { (const float*)d_in[5], (const float*)d_in[9],  (const float*)d_in[13] };
    const float* bs[3]  = { (const float*)d_in[6], (const float*)d_in[10], (const float*)d_in[14] };
    float* out = (float*)d_out;

    // CSR build (dst-grouped adjacency, layer-invariant)
    k_init_deg<<<(N_NODES + 255) / 256, 256>>>();
    k_count<<<(N_EDGES + 255) / 256, 256>>>(ei);
    k_scan<<<1, 1024>>>();
    k_cursor<<<(N_NODES + 255) / 256, 256>>>();
    k_fill<<<(E_TOTAL + 255) / 256, 256>>>(ei);

    const int gemm_grid = (N_NODES + 63) / 64;
    const int warp_grid = (N_NODES * 32 + 255) / 256;  // one warp per node

    for (int l = 0; l < 3; l++) {
        k_gemm<<<gemm_grid, 256>>>(x, W[l], l == 0 ? 1 : 0);
        k_alpha<<<warp_grid, 256>>>(asr[l], ads[l]);
        k_agg<<<warp_grid, 256>>>(bs[l]);
    }

    k_pool<<<N_GRAPHS, 512>>>(batch, out);
}

// round 4
// speedup vs baseline: 1.1841x; 1.1841x over previous
#include <cuda_runtime.h>
#include <cuda_bf16.h>
#include <math.h>

#define N_NODES 50000
#define N_EDGES 600000
#define E_TOTAL (N_EDGES + N_NODES)
#define HID 128
#define N_GRAPHS 64
#define SCAN_BLOCKS ((N_NODES + 1023) / 1024)   // 49

// ---------------- scratch ----------------
__device__ float g_h[N_NODES * HID];
__device__ float g_act[N_NODES * HID];
__device__ float g_as[N_NODES];
__device__ float g_ad[N_NODES];
__device__ int   g_deg[N_NODES];
__device__ int   g_rowptr[N_NODES + 1];
__device__ int   g_cursor[N_NODES];
__device__ int   g_col[E_TOTAL];
__device__ int   g_bsum[64];

// ---------------- CSR build ----------------
__global__ void k_init_deg() {
    int i = blockIdx.x * blockDim.x + threadIdx.x;
    if (i < N_NODES) g_deg[i] = 1;  // self-loop
}

__global__ void k_count(const int* __restrict__ ei) {
    int e = blockIdx.x * blockDim.x + threadIdx.x;
    if (e < N_EDGES) atomicAdd(&g_deg[ei[N_EDGES + e]], 1);
}

// per-block inclusive scan (1024 elems) + block totals
__global__ __launch_bounds__(1024) void k_scan1() {
    __shared__ int sh[1024];
    int tid = threadIdx.x;
    int i = blockIdx.x * 1024 + tid;
    int v = (i < N_NODES) ? g_deg[i] : 0;
    sh[tid] = v;
    __syncthreads();
    #pragma unroll
    for (int off = 1; off < 1024; off <<= 1) {
        int t = (tid >= off) ? sh[tid - off] : 0;
        __syncthreads();
        sh[tid] += t;
        __syncthreads();
    }
    if (i < N_NODES) g_rowptr[i + 1] = sh[tid];
    if (tid == 1023) g_bsum[blockIdx.x] = sh[1023];
}

// exclusive scan of 49 block sums (trivial)
__global__ void k_scan2() {
    int off = 0;
    for (int b = 0; b < SCAN_BLOCKS; b++) {
        int t = g_bsum[b];
        g_bsum[b] = off;
        off += t;
    }
}

// add block offsets; init cursor
__global__ void k_scan3() {
    int i = blockIdx.x * blockDim.x + threadIdx.x;
    if (i == 0) g_rowptr[0] = 0;
    if (i < N_NODES) {
        int val = g_rowptr[i + 1] + g_bsum[i >> 10];
        g_rowptr[i + 1] = val;
        g_cursor[i] = val - g_deg[i];
    }
}

__global__ void k_fill(const int* __restrict__ ei) {
    int idx = blockIdx.x * blockDim.x + threadIdx.x;
    if (idx < N_EDGES) {
        int src = ei[idx];
        int dst = ei[N_EDGES + idx];
        int pos = atomicAdd(&g_cursor[dst], 1);
        g_col[pos] = src;
    } else if (idx < E_TOTAL) {
        int node = idx - N_EDGES;
        int pos = atomicAdd(&g_cursor[node], 1);
        g_col[pos] = node;
    }
}

// ---------------- TF32 helpers ----------------
__device__ __forceinline__ unsigned f2tf(float f) {
    unsigned r;
    asm("cvt.rna.tf32.f32 %0, %1;" : "=r"(r) : "f"(f));
    return r;
}

__device__ __forceinline__ void mma_tf32(float* c, const unsigned* a, unsigned b0, unsigned b1) {
    asm volatile(
        "mma.sync.aligned.m16n8k8.row.col.f32.tf32.tf32.f32 "
        "{%0,%1,%2,%3}, {%4,%5,%6,%7}, {%8,%9}, {%0,%1,%2,%3};"
        : "+f"(c[0]), "+f"(c[1]), "+f"(c[2]), "+f"(c[3])
        : "r"(a[0]), "r"(a[1]), "r"(a[2]), "r"(a[3]), "r"(b0), "r"(b1));
}

// ---------------- GEMM (tensor core, 3xTF32) + fused alpha ----------------
// C[N,128] = A[N,128] @ W[128,128]; alpha_s/alpha_d = C @ a_src / a_dst
// Block: 128 threads (4 warps), 64 rows. Each warp: 16 rows x 128 cols.
#define PA 132  // sA pitch (floats): bank = (4*qr+qc)%32 distinct -> conflict-free
#define PW 136  // sW pitch: bank = (8*qc+qr)%32 distinct -> conflict-free

__global__ __launch_bounds__(128, 2) void k_gemm(const float* __restrict__ X,
                                                 const float* __restrict__ W,
                                                 const float* __restrict__ a_src,
                                                 const float* __restrict__ a_dst,
                                                 int use_x) {
    extern __shared__ float smem[];
    float* sA = smem;                 // [64][PA]
    float* sW = smem + 64 * PA;       // [128][PW]

    const float* A = use_x ? X : g_act;
    int tid = threadIdx.x;
    int lane = tid & 31;
    int wid = tid >> 5;
    int row0 = blockIdx.x * 64;

    // stage W: 128x128, each thread 32 float4 (contiguous per warp-row)
    for (int i = tid; i < 128 * 32; i += 128) {
        int r = i >> 5, cq = i & 31;
        float4 v = reinterpret_cast<const float4*>(W)[r * 32 + cq];
        *reinterpret_cast<float4*>(&sW[r * PW + cq * 4]) = v;
    }
    // stage A tile: 64x128
    for (int i = tid; i < 64 * 32; i += 128) {
        int r = i >> 5, cq = i & 31;
        int grow = row0 + r;
        float4 v = make_float4(0.f, 0.f, 0.f, 0.f);
        if (grow < N_NODES)
            v = reinterpret_cast<const float4*>(A)[grow * 32 + cq];
        *reinterpret_cast<float4*>(&sA[r * PA + cq * 4]) = v;
    }
    __syncthreads();

    int qr = lane >> 2;   // 0..7
    int qc = lane & 3;    // 0..3
    int wr = wid * 16;    // warp's row offset in tile

    float c[16][4];
    #pragma unroll
    for (int t = 0; t < 16; t++) {
        c[t][0] = 0.f; c[t][1] = 0.f; c[t][2] = 0.f; c[t][3] = 0.f;
    }

    #pragma unroll 1
    for (int ks = 0; ks < 16; ks++) {
        int k0 = ks * 8;
        float af[4];
        af[0] = sA[(wr + qr) * PA + k0 + qc];
        af[1] = sA[(wr + qr + 8) * PA + k0 + qc];
        af[2] = sA[(wr + qr) * PA + k0 + qc + 4];
        af[3] = sA[(wr + qr + 8) * PA + k0 + qc + 4];
        unsigned ah[4], al[4];
        #pragma unroll
        for (int j = 0; j < 4; j++) {
            ah[j] = f2tf(af[j]);
            al[j] = f2tf(af[j] - __uint_as_float(ah[j]));
        }
        #pragma unroll
        for (int nt = 0; nt < 16; nt++) {
            int n0 = nt * 8;
            float b0f = sW[(k0 + qc) * PW + n0 + qr];
            float b1f = sW[(k0 + qc + 4) * PW + n0 + qr];
            unsigned bh0 = f2tf(b0f), bh1 = f2tf(b1f);
            unsigned bl0 = f2tf(b0f - __uint_as_float(bh0));
            unsigned bl1 = f2tf(b1f - __uint_as_float(bh1));
            mma_tf32(c[nt], ah, bh0, bh1);   // hi*hi
            mma_tf32(c[nt], al, bh0, bh1);   // lo*hi
            mma_tf32(c[nt], ah, bl0, bl1);   // hi*lo
        }
    }

    // epilogue: store C, fused alpha dots
    int grow0 = row0 + wr + qr;
    int grow1 = grow0 + 8;
    float als0 = 0.f, ald0 = 0.f, als1 = 0.f, ald1 = 0.f;

    #pragma unroll
    for (int nt = 0; nt < 16; nt++) {
        int col0 = nt * 8 + 2 * qc;
        float s0 = __ldg(&a_src[col0]), s1 = __ldg(&a_src[col0 + 1]);
        float d0 = __ldg(&a_dst[col0]), d1 = __ldg(&a_dst[col0 + 1]);
        als0 += c[nt][0] * s0 + c[nt][1] * s1;
        ald0 += c[nt][0] * d0 + c[nt][1] * d1;
        als1 += c[nt][2] * s0 + c[nt][3] * s1;
        ald1 += c[nt][2] * d0 + c[nt][3] * d1;
        if (grow0 < N_NODES)
            *reinterpret_cast<float2*>(&g_h[grow0 * 128 + col0]) = make_float2(c[nt][0], c[nt][1]);
        if (grow1 < N_NODES)
            *reinterpret_cast<float2*>(&g_h[grow1 * 128 + col0]) = make_float2(c[nt][2], c[nt][3]);
    }
    // reduce over qc (4 lanes per quad)
    als0 += __shfl_xor_sync(0xffffffffu, als0, 1);
    als0 += __shfl_xor_sync(0xffffffffu, als0, 2);
    ald0 += __shfl_xor_sync(0xffffffffu, ald0, 1);
    ald0 += __shfl_xor_sync(0xffffffffu, ald0, 2);
    als1 += __shfl_xor_sync(0xffffffffu, als1, 1);
    als1 += __shfl_xor_sync(0xffffffffu, als1, 2);
    ald1 += __shfl_xor_sync(0xffffffffu, ald1, 1);
    ald1 += __shfl_xor_sync(0xffffffffu, ald1, 2);
    if (qc == 0) {
        if (grow0 < N_NODES) { g_as[grow0] = als0; g_ad[grow0] = ald0; }
        if (grow1 < N_NODES) { g_as[grow1] = als1; g_ad[grow1] = ald1; }
    }
}

// ---------------- aggregation: online softmax + weighted gather + bias + ELU ----------------
__global__ __launch_bounds__(256) void k_agg(const float* __restrict__ bias) {
    int w = (blockIdx.x * blockDim.x + threadIdx.x) >> 5;
    int lane = threadIdx.x & 31;
    if (w >= N_NODES) return;

    int beg = g_rowptr[w];
    int end = g_rowptr[w + 1];
    float ad = g_ad[w];

    // pass 1: online max + sum of exp
    float m = -1e30f, ss = 0.f;
    for (int e = beg + lane; e < end; e += 32) {
        int s = g_col[e];
        float v = g_as[s] + ad;
        v = v > 0.f ? v : 0.2f * v;
        if (v > m) { ss = ss * __expf(m - v) + 1.f; m = v; }
        else       { ss += __expf(v - m); }
    }
    // warp combine: M = max m; SS = sum ss_i * exp(m_i - M)
    float M = m;
    #pragma unroll
    for (int off = 16; off > 0; off >>= 1)
        M = fmaxf(M, __shfl_xor_sync(0xffffffffu, M, off));
    float sc = ss * __expf(m - M);
    #pragma unroll
    for (int off = 16; off > 0; off >>= 1)
        sc += __shfl_xor_sync(0xffffffffu, sc, off);
    float inv = 1.f / (sc + 1e-16f);

    // pass 2: weighted gather of h rows (full warp per row)
    float4 acc = make_float4(0.f, 0.f, 0.f, 0.f);
    const float4* h4 = reinterpret_cast<const float4*>(g_h);
    for (int e = beg; e < end; ++e) {
        int s = g_col[e];
        float v = g_as[s] + ad;
        v = v > 0.f ? v : 0.2f * v;
        float wgt = __expf(v - M) * inv;
        float4 hv = h4[s * 32 + lane];
        acc.x += wgt * hv.x;
        acc.y += wgt * hv.y;
        acc.z += wgt * hv.z;
        acc.w += wgt * hv.w;
    }

    float4 bb = reinterpret_cast<const float4*>(bias)[lane];
    acc.x += bb.x; acc.y += bb.y; acc.z += bb.z; acc.w += bb.w;
    acc.x = acc.x > 0.f ? acc.x : (__expf(acc.x) - 1.f);
    acc.y = acc.y > 0.f ? acc.y : (__expf(acc.y) - 1.f);
    acc.z = acc.z > 0.f ? acc.z : (__expf(acc.z) - 1.f);
    acc.w = acc.w > 0.f ? acc.w : (__expf(acc.w) - 1.f);

    reinterpret_cast<float4*>(g_act)[w * 32 + lane] = acc;
}

// ---------------- global mean pool ----------------
__global__ __launch_bounds__(512) void k_pool(const int* __restrict__ batch,
                                              float* __restrict__ out) {
    int g = blockIdx.x;
    int tid = threadIdx.x;
    int sub = tid >> 7;
    int d = tid & 127;

    int lo = 0, hi = N_NODES;
    while (lo < hi) { int mid = (lo + hi) >> 1; if (batch[mid] < g) lo = mid + 1; else hi = mid; }
    int start = lo;
    lo = 0; hi = N_NODES;
    while (lo < hi) { int mid = (lo + hi) >> 1; if (batch[mid] < g + 1) lo = mid + 1; else hi = mid; }
    int stop = lo;

    float s = 0.f;
    for (int i = start + sub; i < stop; i += 4)
        s += g_act[i * 128 + d];

    __shared__ float sm[4][128];
    sm[sub][d] = s;
    __syncthreads();
    if (sub == 0) {
        float tot = sm[0][d] + sm[1][d] + sm[2][d] + sm[3][d];
        int cnt = stop - start;
        out[g * 128 + d] = tot / (float)(cnt > 0 ? cnt : 1);
    }
}

// ---------------- launch ----------------
extern "C" void kernel_launch(void* const* d_in, const int* in_sizes, int n_in,
                              void* d_out, int out_size) {
    const float* x     = (const float*)d_in[0];
    const int*   ei    = (const int*)d_in[1];
    const int*   batch = (const int*)d_in[2];
    const float* W[3]   = { (const float*)d_in[3], (const float*)d_in[7],  (const float*)d_in[11] };
    const float* asr[3] = { (const float*)d_in[4], (const float*)d_in[8],  (const float*)d_in[12] };
    const float* ads[3] = { (const float*)d_in[5], (const float*)d_in[9],  (const float*)d_in[13] };
    const float* bs[3]  = { (const float*)d_in[6], (const float*)d_in[10], (const float*)d_in[14] };
    float* out = (float*)d_out;

    const int smem_bytes = (64 * PA + 128 * PW) * (int)sizeof(float);  // ~103 KB
    cudaFuncSetAttribute(k_gemm, cudaFuncAttributeMaxDynamicSharedMemorySize, smem_bytes);

    // CSR build
    k_init_deg<<<(N_NODES + 255) / 256, 256>>>();
    k_count<<<(N_EDGES + 255) / 256, 256>>>(ei);
    k_scan1<<<SCAN_BLOCKS, 1024>>>();
    k_scan2<<<1, 1>>>();
    k_scan3<<<(N_NODES + 255) / 256, 256>>>();
    k_fill<<<(E_TOTAL + 255) / 256, 256>>>(ei);

    const int gemm_grid = (N_NODES + 63) / 64;
    const int warp_grid = (N_NODES * 32 + 255) / 256;

    for (int l = 0; l < 3; l++) {
        k_gemm<<<gemm_grid, 128, smem_bytes>>>(x, W[l], asr[l], ads[l], l == 0 ? 1 : 0);
        k_agg<<<warp_grid, 256>>>(bs[l]);
    }

    k_pool<<<N_GRAPHS, 512>>>(batch, out);
}

// round 5
// speedup vs baseline: 1.2401x; 1.0473x over previous
#include <cuda_runtime.h>
#include <cuda_bf16.h>
#include <math.h>

#define N_NODES 50000
#define N_EDGES 600000
#define E_TOTAL (N_EDGES + N_NODES)
#define HID 128
#define N_GRAPHS 64
#define SCAN_BLOCKS ((N_NODES + 1023) / 1024)   // 49

// ---------------- scratch ----------------
__device__ float g_h[N_NODES * HID];
__device__ float g_act[N_NODES * HID];
__device__ float g_as[N_NODES];
__device__ float g_ad[N_NODES];
__device__ int   g_deg[N_NODES];
__device__ int   g_rowptr[N_NODES + 1];
__device__ int   g_cursor[N_NODES];
__device__ int   g_col[E_TOTAL];
__device__ int   g_bsum[64];

// ---------------- CSR build ----------------
__global__ void k_init_deg() {
    int i = blockIdx.x * blockDim.x + threadIdx.x;
    if (i < N_NODES) g_deg[i] = 1;  // self-loop
}

__global__ void k_count(const int* __restrict__ ei) {
    int e = blockIdx.x * blockDim.x + threadIdx.x;
    if (e < N_EDGES) atomicAdd(&g_deg[ei[N_EDGES + e]], 1);
}

// per-block inclusive scan (1024 elems) via warp shfl + block totals
__global__ __launch_bounds__(1024) void k_scan1() {
    __shared__ int wsum[32];
    int tid = threadIdx.x;
    int lane = tid & 31;
    int wid = tid >> 5;
    int i = blockIdx.x * 1024 + tid;
    int v = (i < N_NODES) ? g_deg[i] : 0;
    int x = v;
    #pragma unroll
    for (int off = 1; off < 32; off <<= 1) {
        int t = __shfl_up_sync(0xffffffffu, x, off);
        if (lane >= off) x += t;
    }
    if (lane == 31) wsum[wid] = x;
    __syncthreads();
    if (wid == 0) {
        int y = wsum[lane];
        #pragma unroll
        for (int off = 1; off < 32; off <<= 1) {
            int t = __shfl_up_sync(0xffffffffu, y, off);
            if (lane >= off) y += t;
        }
        wsum[lane] = y;
    }
    __syncthreads();
    int incl = x + (wid ? wsum[wid - 1] : 0);
    if (i < N_NODES) g_rowptr[i + 1] = incl;
    if (tid == 1023) g_bsum[blockIdx.x] = incl;
}

// add block offsets (computed in-block) ; init cursor; set rowptr[0]
__global__ __launch_bounds__(256) void k_scan3() {
    __shared__ int s_off;
    int tid = threadIdx.x;
    int g = blockIdx.x >> 2;   // 256-thread block lies in one 1024-chunk
    if (tid < 32) {
        int o = 0;
        for (int j = tid; j < g; j += 32) o += g_bsum[j];
        #pragma unroll
        for (int off = 16; off > 0; off >>= 1)
            o += __shfl_xor_sync(0xffffffffu, o, off);
        if (tid == 0) s_off = o;
    }
    __syncthreads();
    int i = blockIdx.x * 256 + tid;
    if (i == 0) g_rowptr[0] = 0;
    if (i < N_NODES) {
        int val = g_rowptr[i + 1] + s_off;
        g_rowptr[i + 1] = val;
        g_cursor[i] = val - g_deg[i];
    }
}

__global__ void k_fill(const int* __restrict__ ei) {
    int idx = blockIdx.x * blockDim.x + threadIdx.x;
    if (idx < N_EDGES) {
        int src = ei[idx];
        int dst = ei[N_EDGES + idx];
        int pos = atomicAdd(&g_cursor[dst], 1);
        g_col[pos] = src;
    } else if (idx < E_TOTAL) {
        int node = idx - N_EDGES;
        int pos = atomicAdd(&g_cursor[node], 1);
        g_col[pos] = node;
    }
}

// ---------------- TF32 helpers ----------------
__device__ __forceinline__ unsigned f2tf(float f) {
    unsigned r;
    asm("cvt.rna.tf32.f32 %0, %1;" : "=r"(r) : "f"(f));
    return r;
}

__device__ __forceinline__ void mma_tf32(float* c, const unsigned* a, unsigned b0, unsigned b1) {
    asm volatile(
        "mma.sync.aligned.m16n8k8.row.col.f32.tf32.tf32.f32 "
        "{%0,%1,%2,%3}, {%4,%5,%6,%7}, {%8,%9}, {%0,%1,%2,%3};"
        : "+f"(c[0]), "+f"(c[1]), "+f"(c[2]), "+f"(c[3])
        : "r"(a[0]), "r"(a[1]), "r"(a[2]), "r"(a[3]), "r"(b0), "r"(b1));
}

// ---------------- GEMM (tensor core, 3xTF32) + fused alpha ----------------
// Block: 256 threads (8 warps), tile 64 rows x 128 cols.
// Warp grid 2(rows)x4(cols): each warp 32 rows (2 m16 frags) x 32 cols (4 n8 tiles).
#define PA 132  // sA pitch (floats)
#define PW 136  // sW pitch (floats)

__global__ __launch_bounds__(256, 2) void k_gemm(const float* __restrict__ X,
                                                 const float* __restrict__ W,
                                                 const float* __restrict__ a_src,
                                                 const float* __restrict__ a_dst,
                                                 int use_x) {
    extern __shared__ float smem[];
    float* sA = smem;                              // [64][PA]
    float* sW = smem + 64 * PA;                    // [128][PW]
    float* salpha = smem + 64 * PA + 128 * PW;     // [64][2]

    const float* A = use_x ? X : g_act;
    int tid = threadIdx.x;
    int lane = tid & 31;
    int wid = tid >> 5;
    int row0 = blockIdx.x * 64;

    int rg = wid & 1;         // row group: rows rg*32 .. rg*32+31
    int cg = wid >> 1;        // col group: cols cg*32 .. cg*32+31
    int wr = rg * 32;
    int nc0 = cg * 32;

    // zero alpha table
    if (tid < 128) salpha[tid] = 0.f;

    // stage W: 128 rows x 32 float4
    for (int i = tid; i < 128 * 32; i += 256) {
        int r = i >> 5, cq = i & 31;
        float4 v = reinterpret_cast<const float4*>(W)[r * 32 + cq];
        *reinterpret_cast<float4*>(&sW[r * PW + cq * 4]) = v;
    }
    // stage A tile: 64 rows x 32 float4
    for (int i = tid; i < 64 * 32; i += 256) {
        int r = i >> 5, cq = i & 31;
        int grow = row0 + r;
        float4 v = make_float4(0.f, 0.f, 0.f, 0.f);
        if (grow < N_NODES)
            v = reinterpret_cast<const float4*>(A)[grow * 32 + cq];
        *reinterpret_cast<float4*>(&sA[r * PA + cq * 4]) = v;
    }
    __syncthreads();

    int qr = lane >> 2;   // 0..7
    int qc = lane & 3;    // 0..3

    float c[2][4][4];
    #pragma unroll
    for (int f = 0; f < 2; f++)
        #pragma unroll
        for (int nt = 0; nt < 4; nt++) {
            c[f][nt][0] = 0.f; c[f][nt][1] = 0.f; c[f][nt][2] = 0.f; c[f][nt][3] = 0.f;
        }

    #pragma unroll 2
    for (int ks = 0; ks < 16; ks++) {
        int k0 = ks * 8;
        // a fragments: 2 m16 frags (rows wr+f*16 + qr/qr+8)
        unsigned ah[2][4], al[2][4];
        #pragma unroll
        for (int f = 0; f < 2; f++) {
            int rbase = wr + f * 16;
            float af0 = sA[(rbase + qr) * PA + k0 + qc];
            float af1 = sA[(rbase + qr + 8) * PA + k0 + qc];
            float af2 = sA[(rbase + qr) * PA + k0 + qc + 4];
            float af3 = sA[(rbase + qr + 8) * PA + k0 + qc + 4];
            ah[f][0] = f2tf(af0); al[f][0] = f2tf(af0 - __uint_as_float(ah[f][0]));
            ah[f][1] = f2tf(af1); al[f][1] = f2tf(af1 - __uint_as_float(ah[f][1]));
            ah[f][2] = f2tf(af2); al[f][2] = f2tf(af2 - __uint_as_float(ah[f][2]));
            ah[f][3] = f2tf(af3); al[f][3] = f2tf(af3 - __uint_as_float(ah[f][3]));
        }
        #pragma unroll
        for (int nt = 0; nt < 4; nt++) {
            int n0 = nc0 + nt * 8;
            float b0f = sW[(k0 + qc) * PW + n0 + qr];
            float b1f = sW[(k0 + qc + 4) * PW + n0 + qr];
            unsigned bh0 = f2tf(b0f), bh1 = f2tf(b1f);
            unsigned bl0 = f2tf(b0f - __uint_as_float(bh0));
            unsigned bl1 = f2tf(b1f - __uint_as_float(bh1));
            #pragma unroll
            for (int f = 0; f < 2; f++) {
                mma_tf32(c[f][nt], ah[f], bh0, bh1);
                mma_tf32(c[f][nt], al[f], bh0, bh1);
                mma_tf32(c[f][nt], ah[f], bl0, bl1);
            }
        }
    }

    // epilogue: store C + fused alpha partial dots (this warp covers 32 cols)
    float als[4] = {0.f, 0.f, 0.f, 0.f};   // rows: f0:qr, f0:qr+8, f1:qr, f1:qr+8
    float ald[4] = {0.f, 0.f, 0.f, 0.f};

    #pragma unroll
    for (int f = 0; f < 2; f++) {
        int r_lo = row0 + wr + f * 16 + qr;
        int r_hi = r_lo + 8;
        #pragma unroll
        for (int nt = 0; nt < 4; nt++) {
            int col0 = nc0 + nt * 8 + 2 * qc;
            float s0 = __ldg(&a_src[col0]), s1 = __ldg(&a_src[col0 + 1]);
            float d0 = __ldg(&a_dst[col0]), d1 = __ldg(&a_dst[col0 + 1]);
            float* cc = c[f][nt];
            als[f * 2 + 0] += cc[0] * s0 + cc[1] * s1;
            ald[f * 2 + 0] += cc[0] * d0 + cc[1] * d1;
            als[f * 2 + 1] += cc[2] * s0 + cc[3] * s1;
            ald[f * 2 + 1] += cc[2] * d0 + cc[3] * d1;
            if (r_lo < N_NODES)
                *reinterpret_cast<float2*>(&g_h[r_lo * 128 + col0]) = make_float2(cc[0], cc[1]);
            if (r_hi < N_NODES)
                *reinterpret_cast<float2*>(&g_h[r_hi * 128 + col0]) = make_float2(cc[2], cc[3]);
        }
    }
    // reduce over qc (4 lanes per quad), then combine col-groups via smem atomics
    #pragma unroll
    for (int j = 0; j < 4; j++) {
        als[j] += __shfl_xor_sync(0xffffffffu, als[j], 1);
        als[j] += __shfl_xor_sync(0xffffffffu, als[j], 2);
        ald[j] += __shfl_xor_sync(0xffffffffu, ald[j], 1);
        ald[j] += __shfl_xor_sync(0xffffffffu, ald[j], 2);
    }
    if (qc == 0) {
        #pragma unroll
        for (int f = 0; f < 2; f++) {
            int lr_lo = wr + f * 16 + qr;
            atomicAdd(&salpha[lr_lo * 2 + 0], als[f * 2 + 0]);
            atomicAdd(&salpha[lr_lo * 2 + 1], ald[f * 2 + 0]);
            atomicAdd(&salpha[(lr_lo + 8) * 2 + 0], als[f * 2 + 1]);
            atomicAdd(&salpha[(lr_lo + 8) * 2 + 1], ald[f * 2 + 1]);
        }
    }
    __syncthreads();
    if (tid < 64) {
        int grow = row0 + tid;
        if (grow < N_NODES) {
            g_as[grow] = salpha[tid * 2 + 0];
            g_ad[grow] = salpha[tid * 2 + 1];
        }
    }
}

// ---------------- aggregation: online softmax + weighted gather + bias + ELU ----------------
__global__ __launch_bounds__(256) void k_agg(const float* __restrict__ bias) {
    int w = (blockIdx.x * blockDim.x + threadIdx.x) >> 5;
    int lane = threadIdx.x & 31;
    if (w >= N_NODES) return;

    int beg = g_rowptr[w];
    int end = g_rowptr[w + 1];
    float ad = g_ad[w];

    // pass 1: online max + sum of exp (lane-strided)
    float m = -1e30f, ss = 0.f;
    for (int e = beg + lane; e < end; e += 32) {
        int s = g_col[e];
        float v = g_as[s] + ad;
        v = v > 0.f ? v : 0.2f * v;
        if (v > m) { ss = ss * __expf(m - v) + 1.f; m = v; }
        else       { ss += __expf(v - m); }
    }
    float M = m;
    #pragma unroll
    for (int off = 16; off > 0; off >>= 1)
        M = fmaxf(M, __shfl_xor_sync(0xffffffffu, M, off));
    float sc = ss * __expf(m - M);
    #pragma unroll
    for (int off = 16; off > 0; off >>= 1)
        sc += __shfl_xor_sync(0xffffffffu, sc, off);
    float inv = 1.f / (sc + 1e-16f);

    // pass 2: weighted gather, 4x unrolled for MLP
    float4 acc = make_float4(0.f, 0.f, 0.f, 0.f);
    const float4* h4 = reinterpret_cast<const float4*>(g_h);
    int e = beg;
    #pragma unroll 1
    for (; e + 4 <= end; e += 4) {
        int s0 = g_col[e + 0], s1 = g_col[e + 1], s2 = g_col[e + 2], s3 = g_col[e + 3];
        float v0 = g_as[s0] + ad, v1 = g_as[s1] + ad, v2 = g_as[s2] + ad, v3 = g_as[s3] + ad;
        v0 = v0 > 0.f ? v0 : 0.2f * v0;
        v1 = v1 > 0.f ? v1 : 0.2f * v1;
        v2 = v2 > 0.f ? v2 : 0.2f * v2;
        v3 = v3 > 0.f ? v3 : 0.2f * v3;
        float w0 = __expf(v0 - M) * inv, w1 = __expf(v1 - M) * inv;
        float w2 = __expf(v2 - M) * inv, w3 = __expf(v3 - M) * inv;
        float4 h0 = h4[s0 * 32 + lane];
        float4 h1 = h4[s1 * 32 + lane];
        float4 h2 = h4[s2 * 32 + lane];
        float4 h3 = h4[s3 * 32 + lane];
        acc.x += w0 * h0.x + w1 * h1.x + w2 * h2.x + w3 * h3.x;
        acc.y += w0 * h0.y + w1 * h1.y + w2 * h2.y + w3 * h3.y;
        acc.z += w0 * h0.z + w1 * h1.z + w2 * h2.z + w3 * h3.z;
        acc.w += w0 * h0.w + w1 * h1.w + w2 * h2.w + w3 * h3.w;
    }
    for (; e < end; ++e) {
        int s = g_col[e];
        float v = g_as[s] + ad;
        v = v > 0.f ? v : 0.2f * v;
        float wgt = __expf(v - M) * inv;
        float4 hv = h4[s * 32 + lane];
        acc.x += wgt * hv.x;
        acc.y += wgt * hv.y;
        acc.z += wgt * hv.z;
        acc.w += wgt * hv.w;
    }

    float4 bb = reinterpret_cast<const float4*>(bias)[lane];
    acc.x += bb.x; acc.y += bb.y; acc.z += bb.z; acc.w += bb.w;
    acc.x = acc.x > 0.f ? acc.x : (__expf(acc.x) - 1.f);
    acc.y = acc.y > 0.f ? acc.y : (__expf(acc.y) - 1.f);
    acc.z = acc.z > 0.f ? acc.z : (__expf(acc.z) - 1.f);
    acc.w = acc.w > 0.f ? acc.w : (__expf(acc.w) - 1.f);

    reinterpret_cast<float4*>(g_act)[w * 32 + lane] = acc;
}

// ---------------- global mean pool ----------------
__global__ __launch_bounds__(512) void k_pool(const int* __restrict__ batch,
                                              float* __restrict__ out) {
    int g = blockIdx.x;
    int tid = threadIdx.x;
    int sub = tid >> 7;
    int d = tid & 127;

    int lo = 0, hi = N_NODES;
    while (lo < hi) { int mid = (lo + hi) >> 1; if (batch[mid] < g) lo = mid + 1; else hi = mid; }
    int start = lo;
    lo = 0; hi = N_NODES;
    while (lo < hi) { int mid = (lo + hi) >> 1; if (batch[mid] < g + 1) lo = mid + 1; else hi = mid; }
    int stop = lo;

    float s = 0.f;
    for (int i = start + sub; i < stop; i += 4)
        s += g_act[i * 128 + d];

    __shared__ float sm[4][128];
    sm[sub][d] = s;
    __syncthreads();
    if (sub == 0) {
        float tot = sm[0][d] + sm[1][d] + sm[2][d] + sm[3][d];
        int cnt = stop - start;
        out[g * 128 + d] = tot / (float)(cnt > 0 ? cnt : 1);
    }
}

// ---------------- launch ----------------
extern "C" void kernel_launch(void* const* d_in, const int* in_sizes, int n_in,
                              void* d_out, int out_size) {
    const float* x     = (const float*)d_in[0];
    const int*   ei    = (const int*)d_in[1];
    const int*   batch = (const int*)d_in[2];
    const float* W[3]   = { (const float*)d_in[3], (const float*)d_in[7],  (const float*)d_in[11] };
    const float* asr[3] = { (const float*)d_in[4], (const float*)d_in[8],  (const float*)d_in[12] };
    const float* ads[3] = { (const float*)d_in[5], (const float*)d_in[9],  (const float*)d_in[13] };
    const float* bs[3]  = { (const float*)d_in[6], (const float*)d_in[10], (const float*)d_in[14] };
    float* out = (float*)d_out;

    const int smem_bytes = (64 * PA + 128 * PW + 128) * (int)sizeof(float);
    cudaFuncSetAttribute(k_gemm, cudaFuncAttributeMaxDynamicSharedMemorySize, smem_bytes);

    // CSR build
    k_init_deg<<<(N_NODES + 255) / 256, 256>>>();
    k_count<<<(N_EDGES + 255) / 256, 256>>>(ei);
    k_scan1<<<SCAN_BLOCKS, 1024>>>();
    k_scan3<<<(N_NODES + 255) / 256, 256>>>();
    k_fill<<<(E_TOTAL + 255) / 256, 256>>>(ei);

    const int gemm_grid = (N_NODES + 63) / 64;
    const int warp_grid = (N_NODES * 32 + 255) / 256;

    for (int l = 0; l < 3; l++) {
        k_gemm<<<gemm_grid, 256, smem_bytes>>>(x, W[l], asr[l], ads[l], l == 0 ? 1 : 0);
        k_agg<<<warp_grid, 256>>>(bs[l]);
    }

    k_pool<<<N_GRAPHS, 512>>>(batch, out);
}

// round 6
// speedup vs baseline: 1.3461x; 1.0855x over previous
#include <cuda_runtime.h>
#include <cuda_fp16.h>
#include <math.h>

#define N_NODES 50000
#define N_EDGES 600000
#define E_TOTAL (N_EDGES + N_NODES)
#define HID 128
#define N_GRAPHS 64
#define SCAN_BLOCKS ((N_NODES + 1023) / 1024)   // 49

// ---------------- scratch ----------------
__device__ __half g_hh[N_NODES * HID];   // fp16 gather payload (only consumer of h)
__device__ float g_act[N_NODES * HID];   // layer activation (fp32, GEMM input)
__device__ float g_as[N_NODES];
__device__ float g_ad[N_NODES];
__device__ int   g_deg[N_NODES];
__device__ int   g_rowptr[N_NODES + 1];
__device__ int   g_cursor[N_NODES];
__device__ int   g_col[E_TOTAL];
__device__ int   g_bsum[64];

// ---------------- CSR build ----------------
__global__ void k_init_deg() {
    int i = blockIdx.x * blockDim.x + threadIdx.x;
    if (i < N_NODES) g_deg[i] = 1;  // self-loop
}

__global__ void k_count(const int* __restrict__ ei) {
    int e = blockIdx.x * blockDim.x + threadIdx.x;
    if (e < N_EDGES) atomicAdd(&g_deg[ei[N_EDGES + e]], 1);
}

__global__ __launch_bounds__(1024) void k_scan1() {
    __shared__ int wsum[32];
    int tid = threadIdx.x;
    int lane = tid & 31;
    int wid = tid >> 5;
    int i = blockIdx.x * 1024 + tid;
    int v = (i < N_NODES) ? g_deg[i] : 0;
    int x = v;
    #pragma unroll
    for (int off = 1; off < 32; off <<= 1) {
        int t = __shfl_up_sync(0xffffffffu, x, off);
        if (lane >= off) x += t;
    }
    if (lane == 31) wsum[wid] = x;
    __syncthreads();
    if (wid == 0) {
        int y = wsum[lane];
        #pragma unroll
        for (int off = 1; off < 32; off <<= 1) {
            int t = __shfl_up_sync(0xffffffffu, y, off);
            if (lane >= off) y += t;
        }
        wsum[lane] = y;
    }
    __syncthreads();
    int incl = x + (wid ? wsum[wid - 1] : 0);
    if (i < N_NODES) g_rowptr[i + 1] = incl;
    if (tid == 1023) g_bsum[blockIdx.x] = incl;
}

__global__ __launch_bounds__(256) void k_scan3() {
    __shared__ int s_off;
    int tid = threadIdx.x;
    int g = blockIdx.x >> 2;
    if (tid < 32) {
        int o = 0;
        for (int j = tid; j < g; j += 32) o += g_bsum[j];
        #pragma unroll
        for (int off = 16; off > 0; off >>= 1)
            o += __shfl_xor_sync(0xffffffffu, o, off);
        if (tid == 0) s_off = o;
    }
    __syncthreads();
    int i = blockIdx.x * 256 + tid;
    if (i == 0) g_rowptr[0] = 0;
    if (i < N_NODES) {
        int val = g_rowptr[i + 1] + s_off;
        g_rowptr[i + 1] = val;
        g_cursor[i] = val - g_deg[i];
    }
}

__global__ void k_fill(const int* __restrict__ ei) {
    int idx = blockIdx.x * blockDim.x + threadIdx.x;
    if (idx < N_EDGES) {
        int src = ei[idx];
        int dst = ei[N_EDGES + idx];
        int pos = atomicAdd(&g_cursor[dst], 1);
        g_col[pos] = src;
    } else if (idx < E_TOTAL) {
        int node = idx - N_EDGES;
        int pos = atomicAdd(&g_cursor[node], 1);
        g_col[pos] = node;
    }
}

// ---------------- TF32 helpers ----------------
__device__ __forceinline__ unsigned f2tf(float f) {
    unsigned r;
    asm("cvt.rna.tf32.f32 %0, %1;" : "=r"(r) : "f"(f));
    return r;
}

__device__ __forceinline__ void mma_tf32(float* c, const unsigned* a, unsigned b0, unsigned b1) {
    asm volatile(
        "mma.sync.aligned.m16n8k8.row.col.f32.tf32.tf32.f32 "
        "{%0,%1,%2,%3}, {%4,%5,%6,%7}, {%8,%9}, {%0,%1,%2,%3};"
        : "+f"(c[0]), "+f"(c[1]), "+f"(c[2]), "+f"(c[3])
        : "r"(a[0]), "r"(a[1]), "r"(a[2]), "r"(a[3]), "r"(b0), "r"(b1));
}

// ---------------- GEMM (tensor core, 3xTF32) + fused alpha, fp16 h output ----------------
#define PA 132
#define PW 136

__global__ __launch_bounds__(256, 2) void k_gemm(const float* __restrict__ X,
                                                 const float* __restrict__ W,
                                                 const float* __restrict__ a_src,
                                                 const float* __restrict__ a_dst,
                                                 int use_x) {
    extern __shared__ float smem[];
    float* sA = smem;                              // [64][PA]
    float* sW = smem + 64 * PA;                    // [128][PW]
    float* salpha = smem + 64 * PA + 128 * PW;     // [64][2]

    const float* A = use_x ? X : g_act;
    int tid = threadIdx.x;
    int lane = tid & 31;
    int wid = tid >> 5;
    int row0 = blockIdx.x * 64;

    int rg = wid & 1;
    int cg = wid >> 1;
    int wr = rg * 32;
    int nc0 = cg * 32;

    if (tid < 128) salpha[tid] = 0.f;

    for (int i = tid; i < 128 * 32; i += 256) {
        int r = i >> 5, cq = i & 31;
        float4 v = reinterpret_cast<const float4*>(W)[r * 32 + cq];
        *reinterpret_cast<float4*>(&sW[r * PW + cq * 4]) = v;
    }
    for (int i = tid; i < 64 * 32; i += 256) {
        int r = i >> 5, cq = i & 31;
        int grow = row0 + r;
        float4 v = make_float4(0.f, 0.f, 0.f, 0.f);
        if (grow < N_NODES)
            v = reinterpret_cast<const float4*>(A)[grow * 32 + cq];
        *reinterpret_cast<float4*>(&sA[r * PA + cq * 4]) = v;
    }
    __syncthreads();

    int qr = lane >> 2;
    int qc = lane & 3;

    float c[2][4][4];
    #pragma unroll
    for (int f = 0; f < 2; f++)
        #pragma unroll
        for (int nt = 0; nt < 4; nt++) {
            c[f][nt][0] = 0.f; c[f][nt][1] = 0.f; c[f][nt][2] = 0.f; c[f][nt][3] = 0.f;
        }

    #pragma unroll 2
    for (int ks = 0; ks < 16; ks++) {
        int k0 = ks * 8;
        unsigned ah[2][4], al[2][4];
        #pragma unroll
        for (int f = 0; f < 2; f++) {
            int rbase = wr + f * 16;
            float af0 = sA[(rbase + qr) * PA + k0 + qc];
            float af1 = sA[(rbase + qr + 8) * PA + k0 + qc];
            float af2 = sA[(rbase + qr) * PA + k0 + qc + 4];
            float af3 = sA[(rbase + qr + 8) * PA + k0 + qc + 4];
            ah[f][0] = f2tf(af0); al[f][0] = f2tf(af0 - __uint_as_float(ah[f][0]));
            ah[f][1] = f2tf(af1); al[f][1] = f2tf(af1 - __uint_as_float(ah[f][1]));
            ah[f][2] = f2tf(af2); al[f][2] = f2tf(af2 - __uint_as_float(ah[f][2]));
            ah[f][3] = f2tf(af3); al[f][3] = f2tf(af3 - __uint_as_float(ah[f][3]));
        }
        #pragma unroll
        for (int nt = 0; nt < 4; nt++) {
            int n0 = nc0 + nt * 8;
            float b0f = sW[(k0 + qc) * PW + n0 + qr];
            float b1f = sW[(k0 + qc + 4) * PW + n0 + qr];
            unsigned bh0 = f2tf(b0f), bh1 = f2tf(b1f);
            unsigned bl0 = f2tf(b0f - __uint_as_float(bh0));
            unsigned bl1 = f2tf(b1f - __uint_as_float(bh1));
            #pragma unroll
            for (int f = 0; f < 2; f++) {
                mma_tf32(c[f][nt], ah[f], bh0, bh1);
                mma_tf32(c[f][nt], al[f], bh0, bh1);
                mma_tf32(c[f][nt], ah[f], bl0, bl1);
            }
        }
    }

    // epilogue: fp16 h store + fused alpha partial dots
    float als[4] = {0.f, 0.f, 0.f, 0.f};
    float ald[4] = {0.f, 0.f, 0.f, 0.f};
    __half2* hh2 = reinterpret_cast<__half2*>(g_hh);

    #pragma unroll
    for (int f = 0; f < 2; f++) {
        int r_lo = row0 + wr + f * 16 + qr;
        int r_hi = r_lo + 8;
        #pragma unroll
        for (int nt = 0; nt < 4; nt++) {
            int col0 = nc0 + nt * 8 + 2 * qc;
            float s0 = __ldg(&a_src[col0]), s1 = __ldg(&a_src[col0 + 1]);
            float d0 = __ldg(&a_dst[col0]), d1 = __ldg(&a_dst[col0 + 1]);
            float* cc = c[f][nt];
            als[f * 2 + 0] += cc[0] * s0 + cc[1] * s1;
            ald[f * 2 + 0] += cc[0] * d0 + cc[1] * d1;
            als[f * 2 + 1] += cc[2] * s0 + cc[3] * s1;
            ald[f * 2 + 1] += cc[2] * d0 + cc[3] * d1;
            if (r_lo < N_NODES)
                hh2[r_lo * 64 + (col0 >> 1)] = __floats2half2_rn(cc[0], cc[1]);
            if (r_hi < N_NODES)
                hh2[r_hi * 64 + (col0 >> 1)] = __floats2half2_rn(cc[2], cc[3]);
        }
    }
    #pragma unroll
    for (int j = 0; j < 4; j++) {
        als[j] += __shfl_xor_sync(0xffffffffu, als[j], 1);
        als[j] += __shfl_xor_sync(0xffffffffu, als[j], 2);
        ald[j] += __shfl_xor_sync(0xffffffffu, ald[j], 1);
        ald[j] += __shfl_xor_sync(0xffffffffu, ald[j], 2);
    }
    if (qc == 0) {
        #pragma unroll
        for (int f = 0; f < 2; f++) {
            int lr_lo = wr + f * 16 + qr;
            atomicAdd(&salpha[lr_lo * 2 + 0], als[f * 2 + 0]);
            atomicAdd(&salpha[lr_lo * 2 + 1], ald[f * 2 + 0]);
            atomicAdd(&salpha[(lr_lo + 8) * 2 + 0], als[f * 2 + 1]);
            atomicAdd(&salpha[(lr_lo + 8) * 2 + 1], ald[f * 2 + 1]);
        }
    }
    __syncthreads();
    if (tid < 64) {
        int grow = row0 + tid;
        if (grow < N_NODES) {
            g_as[grow] = salpha[tid * 2 + 0];
            g_ad[grow] = salpha[tid * 2 + 1];
        }
    }
}

// ---------------- aggregation: online softmax + fp16 weighted gather + bias + ELU ----------------
__global__ __launch_bounds__(256) void k_agg(const float* __restrict__ bias) {
    int w = (blockIdx.x * blockDim.x + threadIdx.x) >> 5;
    int lane = threadIdx.x & 31;
    if (w >= N_NODES) return;

    int beg = g_rowptr[w];
    int end = g_rowptr[w + 1];
    float ad = g_ad[w];

    // pass 1: online max + sum of exp
    float m = -1e30f, ss = 0.f;
    for (int e = beg + lane; e < end; e += 32) {
        int s = g_col[e];
        float v = g_as[s] + ad;
        v = v > 0.f ? v : 0.2f * v;
        if (v > m) { ss = ss * __expf(m - v) + 1.f; m = v; }
        else       { ss += __expf(v - m); }
    }
    float M = m;
    #pragma unroll
    for (int off = 16; off > 0; off >>= 1)
        M = fmaxf(M, __shfl_xor_sync(0xffffffffu, M, off));
    float sc = ss * __expf(m - M);
    #pragma unroll
    for (int off = 16; off > 0; off >>= 1)
        sc += __shfl_xor_sync(0xffffffffu, sc, off);
    float inv = 1.f / (sc + 1e-16f);

    // pass 2: fp16 weighted gather, 4x unrolled for MLP; lane covers dims [4*lane, 4*lane+3]
    float4 acc = make_float4(0.f, 0.f, 0.f, 0.f);
    const uint2* h2 = reinterpret_cast<const uint2*>(g_hh);
    int e = beg;
    #pragma unroll 1
    for (; e + 4 <= end; e += 4) {
        int s0 = g_col[e + 0], s1 = g_col[e + 1], s2 = g_col[e + 2], s3 = g_col[e + 3];
        float v0 = g_as[s0] + ad, v1 = g_as[s1] + ad, v2 = g_as[s2] + ad, v3 = g_as[s3] + ad;
        v0 = v0 > 0.f ? v0 : 0.2f * v0;
        v1 = v1 > 0.f ? v1 : 0.2f * v1;
        v2 = v2 > 0.f ? v2 : 0.2f * v2;
        v3 = v3 > 0.f ? v3 : 0.2f * v3;
        float w0 = __expf(v0 - M) * inv, w1 = __expf(v1 - M) * inv;
        float w2 = __expf(v2 - M) * inv, w3 = __expf(v3 - M) * inv;
        uint2 r0 = h2[s0 * 32 + lane];
        uint2 r1 = h2[s1 * 32 + lane];
        uint2 r2 = h2[s2 * 32 + lane];
        uint2 r3 = h2[s3 * 32 + lane];
        float2 a0 = __half22float2(*reinterpret_cast<__half2*>(&r0.x));
        float2 b0 = __half22float2(*reinterpret_cast<__half2*>(&r0.y));
        float2 a1 = __half22float2(*reinterpret_cast<__half2*>(&r1.x));
        float2 b1 = __half22float2(*reinterpret_cast<__half2*>(&r1.y));
        float2 a2 = __half22float2(*reinterpret_cast<__half2*>(&r2.x));
        float2 b2 = __half22float2(*reinterpret_cast<__half2*>(&r2.y));
        float2 a3 = __half22float2(*reinterpret_cast<__half2*>(&r3.x));
        float2 b3 = __half22float2(*reinterpret_cast<__half2*>(&r3.y));
        acc.x += w0 * a0.x + w1 * a1.x + w2 * a2.x + w3 * a3.x;
        acc.y += w0 * a0.y + w1 * a1.y + w2 * a2.y + w3 * a3.y;
        acc.z += w0 * b0.x + w1 * b1.x + w2 * b2.x + w3 * b3.x;
        acc.w += w0 * b0.y + w1 * b1.y + w2 * b2.y + w3 * b3.y;
    }
    for (; e < end; ++e) {
        int s = g_col[e];
        float v = g_as[s] + ad;
        v = v > 0.f ? v : 0.2f * v;
        float wgt = __expf(v - M) * inv;
        uint2 r0 = h2[s * 32 + lane];
        float2 a0 = __half22float2(*reinterpret_cast<__half2*>(&r0.x));
        float2 b0 = __half22float2(*reinterpret_cast<__half2*>(&r0.y));
        acc.x += wgt * a0.x;
        acc.y += wgt * a0.y;
        acc.z += wgt * b0.x;
        acc.w += wgt * b0.y;
    }

    float4 bb = reinterpret_cast<const float4*>(bias)[lane];
    acc.x += bb.x; acc.y += bb.y; acc.z += bb.z; acc.w += bb.w;
    acc.x = acc.x > 0.f ? acc.x : (__expf(acc.x) - 1.f);
    acc.y = acc.y > 0.f ? acc.y : (__expf(acc.y) - 1.f);
    acc.z = acc.z > 0.f ? acc.z : (__expf(acc.z) - 1.f);
    acc.w = acc.w > 0.f ? acc.w : (__expf(acc.w) - 1.f);

    reinterpret_cast<float4*>(g_act)[w * 32 + lane] = acc;
}

// ---------------- global mean pool ----------------
__global__ __launch_bounds__(512) void k_pool(const int* __restrict__ batch,
                                              float* __restrict__ out) {
    int g = blockIdx.x;
    int tid = threadIdx.x;
    int sub = tid >> 7;
    int d = tid & 127;

    int lo = 0, hi = N_NODES;
    while (lo < hi) { int mid = (lo + hi) >> 1; if (batch[mid] < g) lo = mid + 1; else hi = mid; }
    int start = lo;
    lo = 0; hi = N_NODES;
    while (lo < hi) { int mid = (lo + hi) >> 1; if (batch[mid] < g + 1) lo = mid + 1; else hi = mid; }
    int stop = lo;

    float s = 0.f;
    for (int i = start + sub; i < stop; i += 4)
        s += g_act[i * 128 + d];

    __shared__ float sm[4][128];
    sm[sub][d] = s;
    __syncthreads();
    if (sub == 0) {
        float tot = sm[0][d] + sm[1][d] + sm[2][d] + sm[3][d];
        int cnt = stop - start;
        out[g * 128 + d] = tot / (float)(cnt > 0 ? cnt : 1);
    }
}

// ---------------- launch ----------------
extern "C" void kernel_launch(void* const* d_in, const int* in_sizes, int n_in,
                              void* d_out, int out_size) {
    const float* x     = (const float*)d_in[0];
    const int*   ei    = (const int*)d_in[1];
    const int*   batch = (const int*)d_in[2];
    const float* W[3]   = { (const float*)d_in[3], (const float*)d_in[7],  (const float*)d_in[11] };
    const float* asr[3] = { (const float*)d_in[4], (const float*)d_in[8],  (const float*)d_in[12] };
    const float* ads[3] = { (const float*)d_in[5], (const float*)d_in[9],  (const float*)d_in[13] };
    const float* bs[3]  = { (const float*)d_in[6], (const float*)d_in[10], (const float*)d_in[14] };
    float* out = (float*)d_out;

    const int smem_bytes = (64 * PA + 128 * PW + 128) * (int)sizeof(float);
    cudaFuncSetAttribute(k_gemm, cudaFuncAttributeMaxDynamicSharedMemorySize, smem_bytes);

    // CSR build
    k_init_deg<<<(N_NODES + 255) / 256, 256>>>();
    k_count<<<(N_EDGES + 255) / 256, 256>>>(ei);
    k_scan1<<<SCAN_BLOCKS, 1024>>>();
    k_scan3<<<(N_NODES + 255) / 256, 256>>>();
    k_fill<<<(E_TOTAL + 255) / 256, 256>>>(ei);

    const int gemm_grid = (N_NODES + 63) / 64;
    const int warp_grid = (N_NODES * 32 + 255) / 256;

    for (int l = 0; l < 3; l++) {
        k_gemm<<<gemm_grid, 256, smem_bytes>>>(x, W[l], asr[l], ads[l], l == 0 ? 1 : 0);
        k_agg<<<warp_grid, 256>>>(bs[l]);
    }

    k_pool<<<N_GRAPHS, 512>>>(batch, out);
}